// round 4
// baseline (speedup 1.0000x reference)
#include <cuda_runtime.h>
#include <cuda_bf16.h>
#include <cstdint>

#define NN 1024
#define BB 32
#define FF 32
#define DD 64
#define HH 64
#define CC 2048   // B*D
#define NP1 1025

// ---------------- scratch (static __device__, no allocs) ----------------
__device__ __nv_bfloat16 g_Abf[NN * NN];    // binarized adjacency, bf16 (exact 0/1)
__device__ float g_m13[NN * CC];            // mu_1 + mu3 + b2
__device__ float g_mu[NN * CC];             // current mu (fp32), [n][b*64+d]
__device__ __nv_bfloat16 g_nu_hi[NN * CC];  // hi part of nu = mu @ W2^T
__device__ __nv_bfloat16 g_nu_lo[NN * CC];  // lo part
__device__ float g_mu3[NN * DD];
__device__ float g_part[8 * CC];            // column-sum partials (one per mtile)
__device__ float g_mumean[BB * DD];
__device__ float g_s2[BB * HH];

// ---------------- helpers ----------------
__device__ __forceinline__ uint32_t smem_u32(const void* p) {
    uint32_t a;
    asm("{ .reg .u64 t; cvta.to.shared.u64 t, %1; cvt.u32.u64 %0, t; }" : "=r"(a) : "l"(p));
    return a;
}
__device__ __forceinline__ void cp16(uint32_t saddr, const void* gaddr) {
    asm volatile("cp.async.cg.shared.global [%0], [%1], 16;\n" :: "r"(saddr), "l"(gaddr));
}

// ---------------- adjacency: binarize to bf16 + mu3 (one adj read) ----------------
__global__ __launch_bounds__(256) void k_graph(const float* __restrict__ adj,
                                               const float* __restrict__ W4,
                                               const float* __restrict__ b4,
                                               const float* __restrict__ W3,
                                               const float* __restrict__ b3) {
    int n = blockIdx.x;
    int tid = threadIdx.x;
    __shared__ float arow[NN];
    __shared__ float part[4][DD];
    __shared__ float mu4s[DD];

    // load row (coalesced float4), store binarized bf16, keep raw in smem
    {
        float4 v = ((const float4*)(adj + (size_t)n * NN))[tid];
        arow[tid * 4 + 0] = v.x;
        arow[tid * 4 + 1] = v.y;
        arow[tid * 4 + 2] = v.z;
        arow[tid * 4 + 3] = v.w;
        union { uint2 u; __nv_bfloat16 h[4]; } pk;
        pk.h[0] = __float2bfloat16(v.x > 0.f ? 1.f : 0.f);
        pk.h[1] = __float2bfloat16(v.y > 0.f ? 1.f : 0.f);
        pk.h[2] = __float2bfloat16(v.z > 0.f ? 1.f : 0.f);
        pk.h[3] = __float2bfloat16(v.w > 0.f ? 1.f : 0.f);
        *(uint2*)(g_Abf + (size_t)n * NN + tid * 4) = pk.u;
    }
    __syncthreads();

    int d = tid & 63, q = tid >> 6;
    float w = W4[d], c0 = b4[d];
    float acc = 0.f;
    for (int m = q; m < NN; m += 4)
        acc += fmaxf(arow[m] * w + c0, 0.f);
    part[q][d] = acc;
    __syncthreads();
    if (tid < DD) mu4s[tid] = part[0][tid] + part[1][tid] + part[2][tid] + part[3][tid];
    __syncthreads();
    if (tid < DD) {
        int d2 = tid;
        float a = b3[d2];
#pragma unroll
        for (int e = 0; e < DD; e++) a += mu4s[e] * W3[d2 * DD + e];
        g_mu3[n * DD + d2] = a;
    }
}

// ---------------- mu_1 + m13 + first nu (fused) ----------------
__global__ __launch_bounds__(256) void k_mu1(const float* __restrict__ xv,
                                             const float* __restrict__ mu1w,
                                             const float* __restrict__ b2,
                                             const float* __restrict__ W2) {
    int n = blockIdx.x;
    __shared__ float xs[BB][FF];
    __shared__ float ws[FF][DD];
    __shared__ float m3[DD];
    __shared__ float mus[CC];
    __shared__ float W2sp[DD * 65];   // padded rows: stride 65 (conflict-free scalar)
    int tid = threadIdx.x;
    for (int i = tid; i < BB * FF; i += 256) {
        int b = i / FF, f = i % FF;
        xs[b][f] = xv[(b * NN + n) * FF + f];
    }
    for (int i = tid; i < FF * DD; i += 256) ws[i / DD][i % DD] = mu1w[i];
    for (int i = tid; i < DD * DD; i += 256) W2sp[(i >> 6) * 65 + (i & 63)] = W2[i];
    if (tid < DD) m3[tid] = g_mu3[n * DD + tid] + b2[tid];
    __syncthreads();
#pragma unroll
    for (int j = 0; j < 8; j++) {
        int c = tid + 256 * j;
        int b = c >> 6, d = c & 63;
        float acc = 0.f;
#pragma unroll
        for (int f = 0; f < FF; f++) acc += xs[b][f] * ws[f][d];
        float r = fmaxf(acc, 0.f);
        g_mu[n * CC + c] = r;
        g_m13[n * CC + c] = r + m3[d];
        mus[c] = r;
    }
    __syncthreads();

    // nu = mu @ W2^T, hi/lo bf16. thread -> (b = tid>>3, dg = tid&7), 8 d each.
    int b = tid >> 3, dg = tid & 7;
    float mur[DD];
#pragma unroll
    for (int e4 = 0; e4 < 16; e4++) {
        float4 v = ((const float4*)(mus + b * DD))[e4];
        mur[4 * e4] = v.x; mur[4 * e4 + 1] = v.y; mur[4 * e4 + 2] = v.z; mur[4 * e4 + 3] = v.w;
    }
    union { uint4 u; __nv_bfloat16 h[8]; } ph, pl;
#pragma unroll
    for (int k = 0; k < 8; k++) {
        int d = dg * 8 + k;
        float acc = 0.f;
#pragma unroll
        for (int e = 0; e < DD; e++) acc += mur[e] * W2sp[d * 65 + e];
        __nv_bfloat16 hi = __float2bfloat16(acc);
        ph.h[k] = hi;
        pl.h[k] = __float2bfloat16(acc - __bfloat162float(hi));
    }
    size_t off = (size_t)n * CC + b * DD + dg * 8;
    *(uint4*)(g_nu_hi + off) = ph.u;
    *(uint4*)(g_nu_lo + off) = pl.u;
}

// ---------------- pool = A @ nu via mma.sync bf16 (hi/lo); mu = relu(m13 + pool) ----------------
// CTA tile 128(m) x 128(c), K-chunk 32, double-buffered cp.async, 8 warps (2x4).
// Epilogue: produce_nu ? (nu hi/lo for next round) : (column-sum partials)
__global__ __launch_bounds__(256) void k_mma(int produce_nu, const float* __restrict__ W2) {
    __shared__ __align__(16) char SB[49152];

    int tid = threadIdx.x;
    int lane = tid & 31, wid = tid >> 5;
    int warpM = wid >> 2, warpN = wid & 3;
    int mbase = blockIdx.y * 128;
    int cbase = blockIdx.x * 128;

    uint32_t sb0 = smem_u32(SB);
    uint32_t asb[2] = { sb0,          sb0 + 8192 };
    uint32_t bhb[2] = { sb0 + 16384,  sb0 + 24576 };
    uint32_t blb[2] = { sb0 + 32768,  sb0 + 40960 };

    float C[16][4];
#pragma unroll
    for (int i = 0; i < 16; i++)
#pragma unroll
        for (int j = 0; j < 4; j++) C[i][j] = 0.f;

    auto load_stage = [&](int ch, int buf) {
#pragma unroll
        for (int t = 0; t < 2; t++) {
            int i = tid + t * 256;
            int m = i >> 2, u = i & 3;
            const __nv_bfloat16* g = g_Abf + (size_t)(mbase + m) * NN + ch * 32 + u * 8;
            uint32_t s = asb[buf] + m * 64 + (((u ^ ((m >> 1) & 3)) & 3) << 4);
            cp16(s, g);
        }
#pragma unroll
        for (int t = 0; t < 2; t++) {
            int i = tid + t * 256;
            int k = i >> 4, u = i & 15;
            int su = (u & 8) | ((u ^ k) & 7);
            size_t go = (size_t)(ch * 32 + k) * CC + cbase + u * 8;
            uint32_t so = k * 256 + (su << 4);
            cp16(bhb[buf] + so, g_nu_hi + go);
            cp16(blb[buf] + so, g_nu_lo + go);
        }
        asm volatile("cp.async.commit_group;\n" ::: "memory");
    };

    load_stage(0, 0);

    for (int ch = 0; ch < 32; ch++) {
        int buf = ch & 1;
        if (ch + 1 < 32) load_stage(ch + 1, buf ^ 1);
        if (ch + 1 < 32) asm volatile("cp.async.wait_group 1;\n" ::: "memory");
        else             asm volatile("cp.async.wait_group 0;\n" ::: "memory");
        __syncthreads();

#pragma unroll
        for (int ks = 0; ks < 2; ks++) {
            uint32_t a[4][4];
#pragma unroll
            for (int mt = 0; mt < 4; mt++) {
                int row = warpM * 64 + mt * 16 + (lane & 7) + ((lane >> 3) & 1) * 8;
                int unit = 2 * ks + (lane >> 4);
                uint32_t addr = asb[buf] + row * 64 + (((unit ^ ((row >> 1) & 3)) & 3) << 4);
                asm volatile("ldmatrix.sync.aligned.m8n8.x4.shared.b16 {%0,%1,%2,%3}, [%4];"
                             : "=r"(a[mt][0]), "=r"(a[mt][1]), "=r"(a[mt][2]), "=r"(a[mt][3])
                             : "r"(addr));
            }
            uint32_t bhf[4][2], blf[4][2];
#pragma unroll
            for (int pair = 0; pair < 2; pair++) {
                int k = ks * 16 + (lane & 7) + ((lane >> 3) & 1) * 8;
                int u = warpN * 4 + pair * 2 + (lane >> 4);
                int su = (u & 8) | ((u ^ k) & 7);
                uint32_t so = k * 256 + (su << 4);
                asm volatile("ldmatrix.sync.aligned.m8n8.x4.trans.shared.b16 {%0,%1,%2,%3}, [%4];"
                             : "=r"(bhf[pair * 2][0]), "=r"(bhf[pair * 2][1]),
                               "=r"(bhf[pair * 2 + 1][0]), "=r"(bhf[pair * 2 + 1][1])
                             : "r"(bhb[buf] + so));
                asm volatile("ldmatrix.sync.aligned.m8n8.x4.trans.shared.b16 {%0,%1,%2,%3}, [%4];"
                             : "=r"(blf[pair * 2][0]), "=r"(blf[pair * 2][1]),
                               "=r"(blf[pair * 2 + 1][0]), "=r"(blf[pair * 2 + 1][1])
                             : "r"(blb[buf] + so));
            }
#pragma unroll
            for (int mt = 0; mt < 4; mt++) {
#pragma unroll
                for (int nt = 0; nt < 4; nt++) {
                    float* c = C[mt * 4 + nt];
                    asm volatile(
                        "mma.sync.aligned.m16n8k16.row.col.f32.bf16.bf16.f32 "
                        "{%0,%1,%2,%3},{%4,%5,%6,%7},{%8,%9},{%0,%1,%2,%3};"
                        : "+f"(c[0]), "+f"(c[1]), "+f"(c[2]), "+f"(c[3])
                        : "r"(a[mt][0]), "r"(a[mt][1]), "r"(a[mt][2]), "r"(a[mt][3]),
                          "r"(bhf[nt][0]), "r"(bhf[nt][1]));
                    asm volatile(
                        "mma.sync.aligned.m16n8k16.row.col.f32.bf16.bf16.f32 "
                        "{%0,%1,%2,%3},{%4,%5,%6,%7},{%8,%9},{%0,%1,%2,%3};"
                        : "+f"(c[0]), "+f"(c[1]), "+f"(c[2]), "+f"(c[3])
                        : "r"(a[mt][0]), "r"(a[mt][1]), "r"(a[mt][2]), "r"(a[mt][3]),
                          "r"(blf[nt][0]), "r"(blf[nt][1]));
                }
            }
        }
        __syncthreads();
    }

    // ---- epilogue part 1: mu = relu(m13 + pool), store fp32 ----
    int g = lane >> 2, tq = lane & 3;
#pragma unroll
    for (int mt = 0; mt < 4; mt++) {
#pragma unroll
        for (int nt = 0; nt < 4; nt++) {
            const float* c = C[mt * 4 + nt];
            int row0 = mbase + warpM * 64 + mt * 16 + g;
            int col = cbase + warpN * 32 + nt * 8 + tq * 2;
            {
                const float2 m = *(const float2*)(g_m13 + (size_t)row0 * CC + col);
                float2 o;
                o.x = fmaxf(m.x + c[0], 0.f);
                o.y = fmaxf(m.y + c[1], 0.f);
                *(float2*)(g_mu + (size_t)row0 * CC + col) = o;
            }
            {
                int row1 = row0 + 8;
                const float2 m = *(const float2*)(g_m13 + (size_t)row1 * CC + col);
                float2 o;
                o.x = fmaxf(m.x + c[2], 0.f);
                o.y = fmaxf(m.y + c[3], 0.f);
                *(float2*)(g_mu + (size_t)row1 * CC + col) = o;
            }
        }
    }

    if (produce_nu) {
        // stage W2 in smem (reuse As region), d-uniform broadcast reads
        float* w2s = (float*)SB;
        for (int i = tid; i < DD * DD; i += 256) w2s[i] = W2[i];
        __syncthreads();   // mu stores visible intra-CTA + w2s ready

        int row = tid >> 1, bsel = tid & 1;
        const float* mp = g_mu + (size_t)(mbase + row) * CC + cbase + bsel * 64;
        float4 mur[16];
#pragma unroll
        for (int e4 = 0; e4 < 16; e4++) mur[e4] = ((const float4*)mp)[e4];
        __nv_bfloat16* nh = g_nu_hi + (size_t)(mbase + row) * CC + cbase + bsel * 64;
        __nv_bfloat16* nl = g_nu_lo + (size_t)(mbase + row) * CC + cbase + bsel * 64;
#pragma unroll
        for (int dg = 0; dg < 8; dg++) {
            union { uint4 u; __nv_bfloat16 h[8]; } ph, pl;
#pragma unroll
            for (int k = 0; k < 8; k++) {
                int d = dg * 8 + k;
                const float4* wr = (const float4*)(w2s + d * DD);
                float acc = 0.f;
#pragma unroll
                for (int e4 = 0; e4 < 16; e4++) {
                    float4 w = wr[e4];
                    acc += mur[e4].x * w.x + mur[e4].y * w.y + mur[e4].z * w.z + mur[e4].w * w.w;
                }
                __nv_bfloat16 hi = __float2bfloat16(acc);
                ph.h[k] = hi;
                pl.h[k] = __float2bfloat16(acc - __bfloat162float(hi));
            }
            *(uint4*)(nh + dg * 8) = ph.u;
            *(uint4*)(nl + dg * 8) = pl.u;
        }
    } else {
        // column-sum partials over this CTA's 128 rows
        float* cs = (float*)SB;
        __syncthreads();   // mu stores visible intra-CTA
        int c = tid & 127, half = tid >> 7;
        const float* mp = g_mu + (size_t)(mbase + half * 64) * CC + cbase + c;
        float s = 0.f;
#pragma unroll 8
        for (int r = 0; r < 64; r++) s += mp[(size_t)r * CC];
        cs[half * 128 + c] = s;
        __syncthreads();
        if (tid < 128)
            g_part[blockIdx.y * CC + cbase + tid] = cs[tid] + cs[128 + tid];
    }
}

// ---------------- mumean + s2, one block per b ----------------
__global__ __launch_bounds__(64) void k_small(const float* __restrict__ option,
                                              const float* __restrict__ Wq1,
                                              const float* __restrict__ bq1,
                                              const float* __restrict__ Wq2,
                                              const float* __restrict__ bq2,
                                              const float* __restrict__ Wreg) {
    int b = blockIdx.x, d = threadIdx.x;
    __shared__ float msum[DD];
    float s = 0.f;
#pragma unroll
    for (int g = 0; g < 8; g++) s += g_part[g * CC + b * DD + d];
    msum[d] = s * (1.0f / (float)NN);
    __syncthreads();
    float acc = bq1[d];
#pragma unroll
    for (int e = 0; e < DD; e++) acc += msum[e] * Wq1[d * DD + e];
    g_mumean[b * DD + d] = fmaxf(acc, 0.f);
    float opt = option[b];
    float acc2 = 0.f;
#pragma unroll
    for (int j = 0; j < DD; j++)
        acc2 += (opt * Wq2[j] + bq2[j]) * Wreg[d * (2 * DD) + DD + j];
    g_s2[b * HH + d] = acc2;
}

// ---------------- final head ----------------
__global__ __launch_bounds__(256) void k_final(const float* __restrict__ Wreg,
                                               const float* __restrict__ breg,
                                               const float* __restrict__ Wq,
                                               const float* __restrict__ bq,
                                               float* __restrict__ out) {
    int b = blockIdx.y;
    int tile = blockIdx.x;
    __shared__ float Wr[HH][DD + 1];
    __shared__ float wqs[HH], s2s[HH], brs[HH];
    __shared__ float vs[8][DD];
    int tid = threadIdx.x;
    for (int i = tid; i < HH * DD; i += 256) {
        int h = i >> 6, j = i & 63;
        Wr[h][j] = Wreg[h * (2 * DD) + j];
    }
    if (tid < HH) {
        wqs[tid] = Wq[tid];
        s2s[tid] = g_s2[b * HH + tid];
        brs[tid] = breg[tid];
    }
    __syncthreads();
    int w = tid >> 5, lane = tid & 31;
    float bqv = bq[0];
    for (int s = 0; s < 8; s++) {
        int i = tile * 64 + w * 8 + s;
        if (i > NN) continue;
        const float* vptr = (i < NN) ? (g_mu + i * CC + b * DD) : (g_mumean + b * DD);
        vs[w][lane]      = vptr[lane];
        vs[w][lane + 32] = vptr[lane + 32];
        __syncwarp();
        float r = 0.f;
#pragma unroll
        for (int hh = 0; hh < 2; hh++) {
            int h = lane + hh * 32;
            float accd = s2s[h] + brs[h];
#pragma unroll
            for (int j = 0; j < DD; j++) accd += vs[w][j] * Wr[h][j];
            r += fmaxf(accd, 0.f) * wqs[h];
        }
#pragma unroll
        for (int off = 16; off; off >>= 1) r += __shfl_down_sync(0xffffffff, r, off);
        if (lane == 0) out[b * NP1 + i] = r + bqv;
        __syncwarp();
    }
}

// ---------------- launch ----------------
extern "C" void kernel_launch(void* const* d_in, const int* in_sizes, int n_in,
                              void* d_out, int out_size) {
    const float* xv     = (const float*)d_in[0];
    const float* option = (const float*)d_in[1];
    const float* adj    = (const float*)d_in[2];
    const float* mu1w   = (const float*)d_in[3];
    const float* W2     = (const float*)d_in[4];
    const float* b2     = (const float*)d_in[5];
    const float* W3     = (const float*)d_in[6];
    const float* b3     = (const float*)d_in[7];
    const float* W4     = (const float*)d_in[8];
    const float* b4     = (const float*)d_in[9];
    const float* Wq1    = (const float*)d_in[10];
    const float* bq1    = (const float*)d_in[11];
    const float* Wq2    = (const float*)d_in[12];
    const float* bq2    = (const float*)d_in[13];
    const float* Wreg   = (const float*)d_in[14];
    const float* breg   = (const float*)d_in[15];
    const float* Wq     = (const float*)d_in[16];
    const float* bq     = (const float*)d_in[17];
    float* out = (float*)d_out;
    (void)in_sizes; (void)n_in; (void)out_size;

    k_graph<<<NN, 256>>>(adj, W4, b4, W3, b3);
    k_mu1<<<NN, 256>>>(xv, mu1w, b2, W2);
    k_mma<<<dim3(CC / 128, NN / 128), 256>>>(1, W2);   // t=1 (+nu)
    k_mma<<<dim3(CC / 128, NN / 128), 256>>>(1, W2);   // t=2 (+nu)
    k_mma<<<dim3(CC / 128, NN / 128), 256>>>(0, W2);   // t=3 (+colsum)
    k_small<<<32, 64>>>(option, Wq1, bq1, Wq2, bq2, Wreg);
    k_final<<<dim3(17, BB), 256>>>(Wreg, breg, Wq, bq, out);
}